// round 16
// baseline (speedup 1.0000x reference)
#include <cuda_runtime.h>
#include <cuda_fp16.h>
#include <math.h>

// Problem constants
#define S_LEN 2048
#define D_DIM 64
#define F_DIM 16
#define NTOK  16384      // B*S
#define DIN   2112       // D + 2*D*F
#define NCH   33         // K chunks of 64
#define TILE_T 64        // tokens per CTA

// ---------------- device scratch ----------------
__device__ float g_f[D_DIM * F_DIM];          // freq_matrix * freq_scale (radians for trig)
__device__ float g_f2[D_DIM * F_DIM];         // f * log2(e)  (softmax in exp2 domain)
__device__ float g_m2[D_DIM * 2];             // per-d (min, max) of g_f2 row
__device__ float g_walpha[4 * D_DIM];         // [h][d] folded alpha weights (incl 1/sqrt(8))
__device__ float g_calpha[4];                 // alpha bias
__device__ __half g_Wh[128 * DIN];            // [o][k] f16: rows 0-63 Wg, 64-127 Wp
__device__ float g_trig[S_LEN * D_DIM * 32];  // [s][d][ sin(16) | cos(16) ]

// ---------------- helpers ----------------
__device__ __forceinline__ unsigned smem_u32(const void* p) {
    unsigned a;
    asm("{ .reg .u64 t; cvta.to.shared.u64 t, %1; cvt.u32.u64 %0, t; }" : "=r"(a) : "l"(p));
    return a;
}
#define SWZ(o) ((o) ^ (((o) >> 3) & 0x70))

__device__ __forceinline__ float ex2a(float x) {
    float y; asm("ex2.approx.f32 %0, %1;" : "=f"(y) : "f"(x)); return y;
}
__device__ __forceinline__ float rcpa(float x) {
    float y; asm("rcp.approx.f32 %0, %1;" : "=f"(y) : "f"(x)); return y;
}
__device__ __forceinline__ void ldsm4(unsigned& r0, unsigned& r1, unsigned& r2, unsigned& r3,
                                      unsigned addr) {
    asm volatile("ldmatrix.sync.aligned.m8n8.x4.shared.b16 {%0,%1,%2,%3}, [%4];"
                 : "=r"(r0), "=r"(r1), "=r"(r2), "=r"(r3) : "r"(addr));
}
__device__ __forceinline__ void mma16816(float* c, unsigned a0, unsigned a1, unsigned a2,
                                         unsigned a3, unsigned b0, unsigned b1) {
    asm volatile(
        "mma.sync.aligned.m16n8k16.row.col.f32.f16.f16.f32 "
        "{%0,%1,%2,%3}, {%4,%5,%6,%7}, {%8,%9}, {%0,%1,%2,%3};"
        : "+f"(c[0]), "+f"(c[1]), "+f"(c[2]), "+f"(c[3])
        : "r"(a0), "r"(a1), "r"(a2), "r"(a3), "r"(b0), "r"(b1));
}

// ---------------- kernel 0: fold tiny weights (1 block, 256 thr) ----------------
__global__ void precompute_small(const float* __restrict__ fm, const float* __restrict__ fs,
                                 const float* __restrict__ Wq, const float* __restrict__ bq,
                                 const float* __restrict__ Wk1,
                                 const float* __restrict__ Wqi, const float* __restrict__ bqi,
                                 const float* __restrict__ Wki) {
    __shared__ float sWcomb[32 * 64];
    __shared__ float sb[32];
    __shared__ float su[32];
    int tid = threadIdx.x;

    const float LOG2E = 1.4426950408889634f;
    for (int i = tid; i < D_DIM * F_DIM; i += 256) {
        float f = fm[i] * fs[i];
        g_f[i] = f;
        g_f2[i] = f * LOG2E;
    }

    for (int i = tid; i < 2048; i += 256) {
        int e = i >> 6, d = i & 63;
        float s = 0.f;
        #pragma unroll 8
        for (int a = 0; a < 32; a++) s += Wqi[e * 32 + a] * Wq[a * 64 + d];
        sWcomb[e * 64 + d] = s;
    }
    if (tid < 32) {
        float s = 0.f, uu = 0.f;
        for (int a = 0; a < 32; a++) {
            s += Wqi[tid * 32 + a] * bq[a];
            uu += Wki[tid * 32 + a] * Wk1[a];
        }
        sb[tid] = s + bqi[tid];
        su[tid] = uu;
    }
    __syncthreads();  // also makes g_f2 global writes visible block-wide

    if (tid < 64) {   // per-d min/max of f2 row
        float mn = 1e30f, mx = -1e30f;
        #pragma unroll
        for (int j = 0; j < 16; j++) {
            float v = g_f2[tid * 16 + j];
            mn = fminf(mn, v);
            mx = fmaxf(mx, v);
        }
        g_m2[2 * tid] = mn;
        g_m2[2 * tid + 1] = mx;
    }

    const float rs8 = 0.35355339059327373f;  // 1/sqrt(8)
    {
        int h = tid >> 6, d = tid & 63;
        float s = 0.f;
        #pragma unroll
        for (int e = 0; e < 8; e++) s += sWcomb[(h * 8 + e) * 64 + d] * su[h * 8 + e];
        g_walpha[h * 64 + d] = s * rs8;
    }
    if (tid < 4) {
        float s = 0.f;
        #pragma unroll
        for (int e = 0; e < 8; e++) s += sb[tid * 8 + e] * su[tid * 8 + e];
        g_calpha[tid] = s * rs8;
    }
}

// ---------------- kernel 1: convert Wg|Wp to f16 [o][k] ----------------
__global__ void convert_wh(const float* __restrict__ Wg, const float* __restrict__ Wp) {
    int i = blockIdx.x * blockDim.x + threadIdx.x;
    if (i >= 128 * DIN) return;
    int o = i / DIN, k = i - o * DIN;
    float v = (o < 64) ? Wg[(size_t)o * DIN + k] : Wp[(size_t)(o - 64) * DIN + k];
    g_Wh[i] = __float2half_rn(v);
}

// ---------------- kernel 2: trig table [s][d][sin16|cos16] f32 ----------------
__global__ void trig_table(const float* __restrict__ phase) {
    int i = blockIdx.x * blockDim.x + threadIdx.x;
    if (i >= S_LEN * D_DIM * F_DIM) return;
    int f = i & 15, d = (i >> 4) & 63, s = i >> 10;
    float t = (float)s * (1.0f / (float)(S_LEN - 1));
    float sig = 6.283185307179586f * t * g_f[d * 16 + f] + phase[d * 16 + f];
    float sv, cv;
    sincosf(sig, &sv, &cv);
    size_t base = ((size_t)s * 64 + d) * 32;
    g_trig[base + f] = sv;
    g_trig[base + 16 + f] = cv;
}

// ---------------- kernel 3: fused feature + HMMA GEMM + gating ----------------
// grid 256 x 256 threads (8 warps), 2 CTAs/SM for phase decorrelation.
// CTA tile: 64 tok x 128 out, K = 33 chunks of 64 (f16).
// A tile [64 tok][64 k] f16 SW128 (8KB), B tile [128 out][64 k] f16 SW128 (16KB).
// Warps 0-3: gate outputs, 4-7: proj; warp tile m16 x n64 via mma.m16n8k16.
// Produce: thread (tau, hh) handles ALL 4 heads over f-subrange [hh*4, hh*4+4);
// exact softmax max via per-d (min,max) of f2; partial-ss quad shfl reduce.
__global__ void __launch_bounds__(256, 2)
fused_hmma(const float* __restrict__ x, const float* __restrict__ bg,
           const float* __restrict__ bp, float* __restrict__ out) {
    __shared__ __align__(1024) char sm[24576];
    const unsigned SM_A = 0, SM_B = 8192;
    unsigned smb = smem_u32(sm);

    int tid = threadIdx.x, wid = tid >> 5, lane = tid & 31;
    int tokBase = blockIdx.x * TILE_T;
    int sBase = tokBase & (S_LEN - 1);  // tile within one sequence (2048 % 64 == 0)

    int tau = tid >> 2, hh = tid & 3;   // token 0-63, f-subrange selector

    // ---- alpha for ALL 4 heads of token tau ----
    float a4[4];
    {
        const float4* xr = (const float4*)(x + (size_t)(tokBase + tau) * 64);
        #pragma unroll
        for (int h = 0; h < 4; h++) {
            float s = __ldg(&g_calpha[h]);
            const float4* wa = (const float4*)(g_walpha + h * 64);
            #pragma unroll
            for (int q = 0; q < 16; q++) {
                float4 xv = __ldg(xr + q);
                float4 wv = __ldg(wa + q);
                s += xv.x * wv.x + xv.y * wv.y + xv.z * wv.z + xv.w * wv.w;
            }
            a4[h] = s;
        }
    }

    // ---- chunk-0 A tile: x -> f16, swizzled (thread writes its 32B quarter-row) ----
    {
        const float4* xr = (const float4*)(x + (size_t)(tokBase + tau) * 64);
        uint4 pay[2];
        __half2* ph = (__half2*)pay;
        #pragma unroll
        for (int j = 0; j < 4; j++) {
            float4 xv = __ldg(xr + hh * 4 + j);
            ph[2 * j]     = __floats2half2_rn(xv.x, xv.y);
            ph[2 * j + 1] = __floats2half2_rn(xv.z, xv.w);
        }
        unsigned o0 = (unsigned)(tau * 128 + hh * 32);
        *(uint4*)(sm + SM_A + SWZ(o0)) = pay[0];
        *(uint4*)(sm + SM_A + SWZ(o0 + 16)) = pay[1];
    }

    // ---- B loader: thread owns 64B of the 16KB chunk (row = tid>>1, half = tid&1) ----
    int brow = tid >> 1, bhalf = tid & 1;
    const __half* bgp = g_Wh + (size_t)brow * DIN + bhalf * 32;
    unsigned bso = (unsigned)(brow * 128 + bhalf * 64);
    uint4 bpre[4];
    #pragma unroll
    for (int j = 0; j < 4; j++) bpre[j] = *(const uint4*)(bgp + j * 8);

    // ---- HMMA mapping (8 warps: 4 m-tiles x 2 halves) ----
    int m0 = (wid & 3) * 16;          // token rows of this warp
    int N0 = (wid >> 2) * 64;         // 0 = gate outputs, 64 = proj outputs
    int i0 = lane & 7, grp = lane >> 3;
    unsigned aRowB = (unsigned)((m0 + i0 + (grp & 1) * 8) * 128);
    unsigned aKadd = (unsigned)((grp >> 1) * 16);
    unsigned bRowB = (unsigned)((N0 + i0 + (grp >> 1) * 8) * 128);
    unsigned bKadd = (unsigned)((grp & 1) * 16);

    float acc[8][4];
    #pragma unroll
    for (int nb = 0; nb < 8; nb++)
        #pragma unroll
        for (int j = 0; j < 4; j++) acc[nb][j] = 0.f;

    uint2 fpayS[2], fpayC[2];  // produced features: [dl] sin-quad / cos-quad (4 f16 each)

    for (int c = 0; c < NCH; c++) {
        __syncthreads();  // previous chunk's mma done reading A/B

        // commit weight chunk c; commit feature chunk c (produced last iter)
        #pragma unroll
        for (int j = 0; j < 4; j++)
            *(uint4*)(sm + SM_B + SWZ(bso + j * 16)) = bpre[j];
        if (c > 0) {
            unsigned ab = (unsigned)(tau * 128 + hh * 8);
            *(uint2*)(sm + SM_A + SWZ(ab))           = fpayS[0];
            *(uint2*)(sm + SM_A + SWZ(ab + 32))      = fpayC[0];
            *(uint2*)(sm + SM_A + SWZ(ab + 64))      = fpayS[1];
            *(uint2*)(sm + SM_A + SWZ(ab + 96))      = fpayC[1];
        }
        __syncthreads();

        bool more = (c + 1 < NCH);
        if (more) {
            // prefetch weight chunk c+1
            #pragma unroll
            for (int j = 0; j < 4; j++)
                bpre[j] = *(const uint4*)(bgp + (size_t)(c + 1) * 64 + j * 8);

            // produce features for chunk c+1 (d = 2c, 2c+1) — overlaps mma below
            #pragma unroll
            for (int dl = 0; dl < 2; dl++) {
                int d = 2 * c + dl;
                const float* tbase = g_trig + ((size_t)(sBase + tau) * 64 + d) * 32;
                float4 ts = __ldg((const float4*)tbase + hh);         // sin f-quad
                float4 tc = __ldg((const float4*)(tbase + 16) + hh);  // cos f-quad
                float2 mm = __ldg((const float2*)(g_m2 + 2 * d));     // (min,max) of f2 row
                float4 fq = __ldg((const float4*)(g_f2 + d * 16) + hh);

                float pr[4][4], psum[4];
                #pragma unroll
                for (int h = 0; h < 4; h++) {
                    float ah = a4[h];
                    float m2 = fmaxf(ah * mm.x, ah * mm.y);  // exact max over f of f2*ah
                    pr[h][0] = ex2a(fmaf(fq.x, ah, -m2));
                    pr[h][1] = ex2a(fmaf(fq.y, ah, -m2));
                    pr[h][2] = ex2a(fmaf(fq.z, ah, -m2));
                    pr[h][3] = ex2a(fmaf(fq.w, ah, -m2));
                    psum[h] = (pr[h][0] + pr[h][1]) + (pr[h][2] + pr[h][3]);
                }
                // full softmax denominators: reduce partials across the token quad
                #pragma unroll
                for (int h = 0; h < 4; h++) {
                    psum[h] += __shfl_xor_sync(0xFFFFFFFFu, psum[h], 1);
                    psum[h] += __shfl_xor_sync(0xFFFFFFFFu, psum[h], 2);
                }
                float inv0 = 0.25f * rcpa(psum[0]), inv1 = 0.25f * rcpa(psum[1]);
                float inv2 = 0.25f * rcpa(psum[2]), inv3 = 0.25f * rcpa(psum[3]);
                float aw[4];
                #pragma unroll
                for (int j = 0; j < 4; j++)
                    aw[j] = fmaf(pr[0][j], inv0,
                            fmaf(pr[1][j], inv1,
                            fmaf(pr[2][j], inv2, pr[3][j] * inv3)));

                __half2* fs_ = (__half2*)&fpayS[dl];
                __half2* fc_ = (__half2*)&fpayC[dl];
                fs_[0] = __floats2half2_rn(ts.x * aw[0], ts.y * aw[1]);
                fs_[1] = __floats2half2_rn(ts.z * aw[2], ts.w * aw[3]);
                fc_[0] = __floats2half2_rn(tc.x * aw[0], tc.y * aw[1]);
                fc_[1] = __floats2half2_rn(tc.z * aw[2], tc.w * aw[3]);
            }
        }

        // ---- HMMA: 4 k16 steps x 8 n8 blocks ----
        #pragma unroll
        for (int ks = 0; ks < 4; ks++) {
            unsigned a0, a1, a2, a3;
            ldsm4(a0, a1, a2, a3, smb + SM_A + SWZ(aRowB + aKadd + ks * 32));
            #pragma unroll
            for (int nb2 = 0; nb2 < 4; nb2++) {
                unsigned b0, b1, b2, b3;
                ldsm4(b0, b1, b2, b3,
                      smb + SM_B + SWZ(bRowB + nb2 * 2048 + bKadd + ks * 32));
                mma16816(acc[nb2 * 2], a0, a1, a2, a3, b0, b1);
                mma16816(acc[nb2 * 2 + 1], a0, a1, a2, a3, b2, b3);
            }
        }
    }

    // ---- epilogue: proj warps stash preacts; gate warps combine + residual ----
    int gr = lane >> 2, qc = (lane & 3) * 2;
    float* smF = (float*)sm;  // [64 tok][64 out] proj preacts (16KB, reuses A|B)

    __syncthreads();
    if (N0 == 64) {
        #pragma unroll
        for (int nb = 0; nb < 8; nb++) {
            int o = nb * 8 + qc;
            *(float2*)(smF + (m0 + gr) * 64 + o)     = make_float2(acc[nb][0], acc[nb][1]);
            *(float2*)(smF + (m0 + gr + 8) * 64 + o) = make_float2(acc[nb][2], acc[nb][3]);
        }
    }
    __syncthreads();
    if (N0 == 0) {
        #pragma unroll
        for (int nb = 0; nb < 8; nb++) {
            int o = nb * 8 + qc;
            float2 bgv = *(const float2*)(bg + o);
            float2 bpv = *(const float2*)(bp + o);
            #pragma unroll
            for (int half = 0; half < 2; half++) {
                int tl = m0 + gr + half * 8;
                int tok = tokBase + tl;
                float gv0 = acc[nb][2 * half]     + bgv.x;
                float gv1 = acc[nb][2 * half + 1] + bgv.y;
                float2 pv = *(const float2*)(smF + tl * 64 + o);
                pv.x += bpv.x; pv.y += bpv.y;
                float2 xv = __ldg((const float2*)(x + (size_t)tok * 64 + o));
                float2 ov;
                ov.x = xv.x + __frcp_rn(1.f + __expf(-gv0)) *
                              (pv.x * __frcp_rn(1.f + __expf(-pv.x)));
                ov.y = xv.y + __frcp_rn(1.f + __expf(-gv1)) *
                              (pv.y * __frcp_rn(1.f + __expf(-pv.y)));
                *(float2*)(out + (size_t)tok * 64 + o) = ov;
            }
        }
    }
}

// ---------------- launch ----------------
extern "C" void kernel_launch(void* const* d_in, const int* in_sizes, int n_in,
                              void* d_out, int out_size) {
    const float* x     = (const float*)d_in[0];
    const float* fm    = (const float*)d_in[1];
    const float* phase = (const float*)d_in[2];
    const float* fsc   = (const float*)d_in[3];
    const float* Wq    = (const float*)d_in[4];
    const float* bq    = (const float*)d_in[5];
    const float* Wk1   = (const float*)d_in[6];
    // d_in[7] = bk1: constant along softmax axis -> cancels
    const float* Wqi   = (const float*)d_in[8];
    const float* bqi   = (const float*)d_in[9];
    const float* Wki   = (const float*)d_in[10];
    // d_in[11] = bki: cancels in softmax
    const float* Wg    = (const float*)d_in[12];
    const float* bg    = (const float*)d_in[13];
    const float* Wp    = (const float*)d_in[14];
    const float* bp    = (const float*)d_in[15];
    float* out = (float*)d_out;

    precompute_small<<<1, 256>>>(fm, fsc, Wq, bq, Wk1, Wqi, bqi, Wki);
    convert_wh<<<(128 * DIN + 255) / 256, 256>>>(Wg, Wp);
    trig_table<<<(S_LEN * D_DIM * F_DIM + 255) / 256, 256>>>(phase);
    fused_hmma<<<NTOK / TILE_T, 256>>>(x, bg, bp, out);
}